// round 6
// baseline (speedup 1.0000x reference)
#include <cuda_runtime.h>
#include <math.h>
#include <stdint.h>

#define BN 4
#define NN 256
#define EFD 256
#define MD 128
#define CLS 600

// ---------------- device scratch (static, zero-init) ----------------
__device__ float g_mraw[(size_t)BN * NN * NN * MD];   // 128 MB
__device__ float g_sA[BN * NN * NN];
__device__ float g_sB[BN * NN * NN];
__device__ float g_nf[BN * NN * MD];
__device__ float g_anf[BN * NN * MD];
__device__ float g_msum[BN * NN * MD];
__device__ float g_Wem[EFD * MD];   // tf32(W_er @ W_msg_bot), row-major [k][c]
__device__ float g_Wel[EFD * MD];   // tf32(W_er @ W_l1)
__device__ float g_Wl1c[MD * MD];   // tf32(W_l1)
__device__ float g_bem[MD];         // b_er @ W_msg_bot
__device__ float g_bel[MD];         // b_er @ W_l1 + b_l1

__device__ __forceinline__ float sigmoidf_(float x) { return 1.0f / (1.0f + __expf(-x)); }

__device__ __forceinline__ float tf32f(float v) {
    uint32_t u;
    asm("cvt.rna.tf32.f32 %0, %1;" : "=r"(u) : "f"(v));
    return __uint_as_float(u);
}

__device__ __forceinline__ void mma8(float* c, const uint32_t* a, const uint32_t* b) {
    asm volatile(
        "mma.sync.aligned.m16n8k8.row.col.f32.tf32.tf32.f32 "
        "{%0,%1,%2,%3}, {%4,%5,%6,%7}, {%8,%9}, {%0,%1,%2,%3};"
        : "+f"(c[0]), "+f"(c[1]), "+f"(c[2]), "+f"(c[3])
        : "r"(a[0]), "r"(a[1]), "r"(a[2]), "r"(a[3]), "r"(b[0]), "r"(b[1]));
}

__device__ __forceinline__ uint32_t smem_u32(const void* p) {
    uint32_t a;
    asm("{ .reg .u64 t; cvta.to.shared.u64 t, %1; cvt.u32.u64 %0, t; }" : "=r"(a) : "l"(p));
    return a;
}
__device__ __forceinline__ void cpa16(uint32_t dst, const float* src) {
    asm volatile("cp.async.cg.shared.global [%0], [%1], 16;" :: "r"(dst), "l"(src));
}
#define CPA_COMMIT() asm volatile("cp.async.commit_group;" ::: "memory")
#define CPA_WAIT0()  asm volatile("cp.async.wait_group 0;" ::: "memory")

// ================= prep: zero adj + fold weights + node features =================
__global__ __launch_bounds__(128) void k_prep(
    float* __restrict__ out,
    const float* __restrict__ nfeat,
    const float* __restrict__ W_er, const float* __restrict__ b_er,
    const float* __restrict__ W_nr, const float* __restrict__ b_nr,
    const float* __restrict__ W_msg, const float* __restrict__ b_msg,
    const float* __restrict__ W_l1, const float* __restrict__ b_l1)
{
    const int t = threadIdx.x;
    const int blk = blockIdx.x;
    __shared__ float xs[4][EFD];
    __shared__ float nfs[4][MD];

    if (blk < 512) {                       // zero pred_adj region (1 MB)
        int idx = blk * 128 + t;
        reinterpret_cast<float4*>(out)[idx] = make_float4(0.f, 0.f, 0.f, 0.f);
    } else if (blk < 769) {                // fold
        const int k = blk - 512;           // 0..256
        const int c = t;
        if (k < EFD) {
            float am = 0.f, al = 0.f;
            #pragma unroll 8
            for (int j = 0; j < MD; j++) {
                float a = W_er[k * MD + j];
                am = fmaf(a, W_msg[(MD + j) * MD + c], am);
                al = fmaf(a, W_l1[j * MD + c], al);
            }
            g_Wem[k * MD + c] = tf32f(am);
            g_Wel[k * MD + c] = tf32f(al);
            if (k < MD)
                g_Wl1c[k * MD + c] = tf32f(W_l1[k * MD + c]);
        } else {
            float am = 0.f, al = 0.f;
            #pragma unroll 8
            for (int j = 0; j < MD; j++) {
                float a = b_er[j];
                am = fmaf(a, W_msg[(MD + j) * MD + c], am);
                al = fmaf(a, W_l1[j * MD + c], al);
            }
            g_bem[c] = am;
            g_bel[c] = al + b_l1[c];
        }
    } else {                               // node features: 4 nodes per block
        const int g0 = (blk - 769) * 4;
        {
            const float4* src = reinterpret_cast<const float4*>(nfeat + (size_t)g0 * EFD);
            float4* dst = reinterpret_cast<float4*>(&xs[0][0]);
            #pragma unroll
            for (int j = 0; j < 2; j++) dst[t + 128 * j] = src[t + 128 * j];
        }
        __syncthreads();
        float acc[4];
        #pragma unroll
        for (int n = 0; n < 4; n++) acc[n] = 0.f;
        #pragma unroll 8
        for (int k = 0; k < EFD; k++) {
            float wv = W_nr[k * MD + t];
            #pragma unroll
            for (int n = 0; n < 4; n++) acc[n] = fmaf(xs[n][k], wv, acc[n]);
        }
        float bv = b_nr[t];
        #pragma unroll
        for (int n = 0; n < 4; n++) {
            float v = acc[n] + bv;
            nfs[n][t] = v;
            g_nf[(size_t)(g0 + n) * MD + t] = v;
        }
        __syncthreads();
        #pragma unroll
        for (int n = 0; n < 4; n++) acc[n] = 0.f;
        #pragma unroll 8
        for (int k = 0; k < MD; k++) {
            float wv = W_msg[k * MD + t];   // top half rows of W_msg
            #pragma unroll
            for (int n = 0; n < 4; n++) acc[n] = fmaf(nfs[n][k], wv, acc[n]);
        }
        bv = b_msg[t];
        #pragma unroll
        for (int n = 0; n < 4; n++)
            g_anf[(size_t)(g0 + n) * MD + t] = acc[n] + bv;
    }
}

// ================= edge kernel: tf32 mma.sync + cp.async pipeline =================
// CTA: 64 edges (4 recv x 16 send) x N=256 (0-127: W_em, 128-255: W_el).
// 256 threads, 8 warps: mg=wid>>2 (rows mg*32..+31), ng=wid&3 (cols ng*64..+63).
// K = 256 in 8 chunks of 32, double-buffered (B via cp.async, A via regs).
#define AP 36      // A smem pitch
#define BP 264     // B smem pitch
__global__ __launch_bounds__(256, 2) void k_edge_mma(
    const float* __restrict__ X,
    const int* __restrict__ hn, const int* __restrict__ on,
    const float* __restrict__ W_l2, const float* __restrict__ b_l2)
{
    const int b  = blockIdx.z;
    const int V  = hn[b] + on[b];
    const int i0 = blockIdx.y * 4;
    const int w0 = blockIdx.x * 16;
    if (i0 >= V || w0 >= V) return;

    __shared__ float As[2][64][AP];        // 18.4 KB
    __shared__ float Bs[2][32][BP];        // 67.6 KB (buf0 reused as mstage[64][132])
    __shared__ float lpart[2][64];
    __shared__ float bem_s[MD], bel_s[MD], u_s[MD];

    const int t    = threadIdx.x;
    const int wid  = t >> 5;
    const int lane = t & 31;
    const int g    = lane >> 2;
    const int l    = lane & 3;
    const int mg   = wid >> 2;             // 0..1
    const int ng   = wid & 3;              // 0..3

    if (t < 128) { bem_s[t] = g_bem[t]; bel_s[t] = g_bel[t]; u_s[t] = W_l2[t]; }

    const int arow  = t >> 2;              // 0..63
    const int apart = t & 3;
    const int ari = arow >> 4, awi = arow & 15;
    const float* xrow = X + (size_t)((b * NN + i0 + ari) * NN + w0 + awi) * EFD + apart * 8;

    // B cp.async targets for this thread (8 float4 per buffer)
    uint32_t bdst[8];
    const float* bsrc_base[8];
    #pragma unroll
    for (int jj = 0; jj < 8; jj++) {
        int idx = jj * 256 + t;            // 0..2047
        int row = idx >> 6;                // 0..31
        int c4  = idx & 63;                // 0..63
        bdst[jj] = smem_u32(&Bs[0][row][c4 * 4]);
        bsrc_base[jj] = (c4 < 32) ? &g_Wem[(size_t)row * MD + c4 * 4]
                                  : &g_Wel[(size_t)row * MD + (c4 - 32) * 4];
    }
    const uint32_t bufstride = (uint32_t)(32 * BP * 4);

    float acc[2][8][4];
    #pragma unroll
    for (int m = 0; m < 2; m++)
        #pragma unroll
        for (int n = 0; n < 8; n++)
            #pragma unroll
            for (int q = 0; q < 4; q++) acc[m][n][q] = 0.f;

    float a0r[8];
    // prologue: chunk 0
    #pragma unroll
    for (int jj = 0; jj < 8; jj++) a0r[jj] = xrow[(jj >> 2) * 4 + (jj & 3)];
    #pragma unroll
    for (int jj = 0; jj < 8; jj++) cpa16(bdst[jj], bsrc_base[jj]);
    CPA_COMMIT();
    #pragma unroll
    for (int jj = 0; jj < 8; jj++) As[0][arow][apart * 8 + jj] = tf32f(a0r[jj]);
    CPA_WAIT0();
    __syncthreads();

    #pragma unroll 1
    for (int kc = 0; kc < 8; kc++) {
        const int cur = kc & 1, nxt = cur ^ 1;
        if (kc < 7) {
            #pragma unroll
            for (int jj = 0; jj < 8; jj++)
                cpa16(bdst[jj] + nxt * bufstride, bsrc_base[jj] + (size_t)(kc + 1) * 32 * MD);
            CPA_COMMIT();
            #pragma unroll
            for (int jj = 0; jj < 8; jj++)
                a0r[jj] = xrow[(kc + 1) * 32 + (jj >> 2) * 4 + (jj & 3)];
        }
        #pragma unroll
        for (int kb = 0; kb < 32; kb += 8) {
            uint32_t af[2][4];
            #pragma unroll
            for (int m = 0; m < 2; m++) {
                int r0 = mg * 32 + m * 16;
                af[m][0] = __float_as_uint(As[cur][r0 + g][kb + l]);
                af[m][1] = __float_as_uint(As[cur][r0 + g + 8][kb + l]);
                af[m][2] = __float_as_uint(As[cur][r0 + g][kb + l + 4]);
                af[m][3] = __float_as_uint(As[cur][r0 + g + 8][kb + l + 4]);
            }
            #pragma unroll
            for (int n = 0; n < 8; n++) {
                uint32_t bf[2];
                int nb = ng * 64 + n * 8 + g;
                bf[0] = __float_as_uint(Bs[cur][kb + l][nb]);
                bf[1] = __float_as_uint(Bs[cur][kb + l + 4][nb]);
                mma8(acc[0][n], af[0], bf);
                mma8(acc[1][n], af[1], bf);
            }
        }
        if (kc < 7) {
            #pragma unroll
            for (int jj = 0; jj < 8; jj++) As[nxt][arow][apart * 8 + jj] = tf32f(a0r[jj]);
            CPA_WAIT0();
        }
        __syncthreads();
    }

    const float bl2v = b_l2[0];
    if (ng >= 2) {
        // ---- link path: p[row] = sum_c relu(acc + bel[c]) * u[c] ----
        float p[4] = {0.f, 0.f, 0.f, 0.f};
        #pragma unroll
        for (int m = 0; m < 2; m++)
            #pragma unroll
            for (int n = 0; n < 8; n++) {
                int cb = (ng - 2) * 64 + n * 8 + 2 * l;
                float u0 = u_s[cb], u1 = u_s[cb + 1];
                float e0 = bel_s[cb], e1 = bel_s[cb + 1];
                p[m*2+0] += fmaxf(acc[m][n][0] + e0, 0.f) * u0 + fmaxf(acc[m][n][1] + e1, 0.f) * u1;
                p[m*2+1] += fmaxf(acc[m][n][2] + e0, 0.f) * u0 + fmaxf(acc[m][n][3] + e1, 0.f) * u1;
            }
        #pragma unroll
        for (int q = 0; q < 4; q++) {
            p[q] += __shfl_xor_sync(0xffffffffu, p[q], 1);
            p[q] += __shfl_xor_sync(0xffffffffu, p[q], 2);
        }
        if (l == 0) {
            lpart[ng - 2][mg * 32 + g]      = p[0];
            lpart[ng - 2][mg * 32 + g + 8]  = p[1];
            lpart[ng - 2][mg * 32 + 16 + g] = p[2];
            lpart[ng - 2][mg * 32 + 24 + g] = p[3];
        }
    } else {
        // ---- message path: stage raw accs ----
        float* mst = &Bs[0][0][0];         // [64][132]
        #pragma unroll
        for (int m = 0; m < 2; m++) {
            int r0 = mg * 32 + m * 16 + g;
            #pragma unroll
            for (int n = 0; n < 8; n++) {
                int cb = ng * 64 + n * 8 + 2 * l;
                mst[r0 * 132 + cb]           = acc[m][n][0];
                mst[r0 * 132 + cb + 1]       = acc[m][n][1];
                mst[(r0 + 8) * 132 + cb]     = acc[m][n][2];
                mst[(r0 + 8) * 132 + cb + 1] = acc[m][n][3];
            }
        }
    }
    __syncthreads();

    if (t < 64) {
        int ri2 = t >> 4, wi2 = t & 15;
        if (i0 + ri2 < V && w0 + wi2 < V)
            g_sA[(b * NN + i0 + ri2) * NN + w0 + wi2] = lpart[0][t] + lpart[1][t] + bl2v;
    }
    {
        int row = t >> 2, part = t & 3;
        int ri2 = row >> 4, wi2 = row & 15;
        if (i0 + ri2 < V && w0 + wi2 < V) {
            const float* ap = g_anf + (size_t)(b * NN + w0 + wi2) * MD + part * 32;
            float* mp = g_mraw + (size_t)((b * NN + i0 + ri2) * NN + w0 + wi2) * MD + part * 32;
            const float* mst = &Bs[0][0][0] + row * 132 + part * 32;
            #pragma unroll
            for (int jj = 0; jj < 8; jj++) {
                float4 m4 = *(const float4*)(mst + jj * 4);
                float4 a4 = *(const float4*)(ap + jj * 4);
                float4 e4 = *(const float4*)(&bem_s[part * 32 + jj * 4]);
                float4 v;
                v.x = fmaxf(m4.x + e4.x + a4.x, 0.f);
                v.y = fmaxf(m4.y + e4.y + a4.y, 0.f);
                v.z = fmaxf(m4.z + e4.z + a4.z, 0.f);
                v.w = fmaxf(m4.w + e4.w + a4.w, 0.f);
                *(float4*)(mp + jj * 4) = v;
            }
        }
    }
}

// ================= round kernel: fully-resident tf32 mma.sync =================
// s_next[i,w] = relu( (sig(s_prev[w,i])*m_raw[w,i]) @ W_l1 + b_l1 ) . W_l2 + b_l2
// CTA: 64 edges x N=128, full K=128 resident. ONE sync, 16 uninterrupted k-steps.
#define RAP 132
#define RBPf 136
__global__ __launch_bounds__(256, 2) void k_round_mma(
    int pass,
    const int* __restrict__ hn, const int* __restrict__ on,
    const float* __restrict__ b_l1,
    const float* __restrict__ W_l2, const float* __restrict__ b_l2,
    float* __restrict__ out_adj)
{
    const int b  = blockIdx.z;
    const int V  = hn[b] + on[b];
    const int i0 = blockIdx.y * 4;
    const int w0 = blockIdx.x * 16;
    if (i0 >= V || w0 >= V) return;

    const float* sprev = (pass == 1) ? g_sA : g_sB;
    float*       snext = (pass == 1) ? g_sB : g_sA;

    __shared__ float As[64][RAP];          // 33.8 KB (full gated A)
    __shared__ float Bs[MD][RBPf];         // 69.6 KB (full W_l1)
    __shared__ float lpart[4][64];
    __shared__ float gates[64];
    __shared__ float bl1_s[MD], u_s[MD];

    const int t    = threadIdx.x;
    const int wid  = t >> 5;
    const int lane = t & 31;
    const int g    = lane >> 2;
    const int l    = lane & 3;
    const int mg   = wid >> 2;
    const int ng   = wid & 3;

    if (t < 128) { bl1_s[t] = b_l1[t]; u_s[t] = W_l2[t]; }
    if (t < 64) {
        int ri = t >> 4, wi = t & 15;
        bool ok = (i0 + ri < V) && (w0 + wi < V);
        gates[t] = ok ? sigmoidf_(sprev[(b * NN + w0 + wi) * NN + i0 + ri]) : 0.f;
    }
    __syncthreads();

    // fill full B: 4096 float4 / 256 threads = 16 each
    #pragma unroll
    for (int jj = 0; jj < 16; jj++) {
        int idx = jj * 256 + t;
        int row = idx >> 5, c4 = idx & 31;
        *(float4*)(&Bs[row][c4 * 4]) = *(const float4*)(&g_Wl1c[(size_t)row * MD + c4 * 4]);
    }
    // fill full A: thread owns row t>>2, quarter t&3 (32 k-values)
    {
        const int arow  = t >> 2;
        const int apart = t & 3;
        const int ari = arow >> 4, awi = arow & 15;
        const float gv = gates[arow];
        const float* mrow = g_mraw
            + (size_t)((b * NN + w0 + awi) * NN + i0 + ari) * MD + apart * 32;
        #pragma unroll
        for (int jj = 0; jj < 8; jj++) {
            float4 v = *(const float4*)(mrow + jj * 4);
            As[arow][apart * 32 + jj * 4 + 0] = tf32f(v.x * gv);
            As[arow][apart * 32 + jj * 4 + 1] = tf32f(v.y * gv);
            As[arow][apart * 32 + jj * 4 + 2] = tf32f(v.z * gv);
            As[arow][apart * 32 + jj * 4 + 3] = tf32f(v.w * gv);
        }
    }
    __syncthreads();

    float acc[2][4][4];
    #pragma unroll
    for (int m = 0; m < 2; m++)
        #pragma unroll
        for (int n = 0; n < 4; n++)
            #pragma unroll
            for (int q = 0; q < 4; q++) acc[m][n][q] = 0.f;

    #pragma unroll
    for (int kb = 0; kb < MD; kb += 8) {
        uint32_t af[2][4];
        #pragma unroll
        for (int m = 0; m < 2; m++) {
            int r0 = mg * 32 + m * 16;
            af[m][0] = __float_as_uint(As[r0 + g][kb + l]);
            af[m][1] = __float_as_uint(As[r0 + g + 8][kb + l]);
            af[m][2] = __float_as_uint(As[r0 + g][kb + l + 4]);
            af[m][3] = __float_as_uint(As[r0 + g + 8][kb + l + 4]);
        }
        #pragma unroll
        for (int n = 0; n < 4; n++) {
            uint32_t bf[2];
            int nb = ng * 32 + n * 8 + g;
            bf[0] = __float_as_uint(Bs[kb + l][nb]);
            bf[1] = __float_as_uint(Bs[kb + l + 4][nb]);
            mma8(acc[0][n], af[0], bf);
            mma8(acc[1][n], af[1], bf);
        }
    }

    // link reduction: each warp owns 32 cols
    {
        float p[4] = {0.f, 0.f, 0.f, 0.f};
        #pragma unroll
        for (int m = 0; m < 2; m++)
            #pragma unroll
            for (int n = 0; n < 4; n++) {
                int cb = ng * 32 + n * 8 + 2 * l;
                float u0 = u_s[cb], u1 = u_s[cb + 1];
                float e0 = bl1_s[cb], e1 = bl1_s[cb + 1];
                p[m*2+0] += fmaxf(acc[m][n][0] + e0, 0.f) * u0 + fmaxf(acc[m][n][1] + e1, 0.f) * u1;
                p[m*2+1] += fmaxf(acc[m][n][2] + e0, 0.f) * u0 + fmaxf(acc[m][n][3] + e1, 0.f) * u1;
            }
        #pragma unroll
        for (int q = 0; q < 4; q++) {
            p[q] += __shfl_xor_sync(0xffffffffu, p[q], 1);
            p[q] += __shfl_xor_sync(0xffffffffu, p[q], 2);
        }
        if (l == 0) {
            lpart[ng][mg * 32 + g]      = p[0];
            lpart[ng][mg * 32 + g + 8]  = p[1];
            lpart[ng][mg * 32 + 16 + g] = p[2];
            lpart[ng][mg * 32 + 24 + g] = p[3];
        }
    }
    __syncthreads();
    if (t < 64) {
        int ri2 = t >> 4, wi2 = t & 15;
        if (i0 + ri2 < V && w0 + wi2 < V) {
            int d = (b * NN + i0 + ri2) * NN + w0 + wi2;
            float sv = (lpart[0][t] + lpart[1][t]) + (lpart[2][t] + lpart[3][t]) + b_l2[0];
            snext[d] = sv;
            if (out_adj) out_adj[d] = sv;
        }
    }
}

// ---------------- m_sum[b,i] = sum_w sigmoid(s2[i,w]) * m_raw[i,w,:] ----------------
__global__ __launch_bounds__(128) void k_msum(const int* __restrict__ hn, const int* __restrict__ on) {
    const int b = blockIdx.y;
    const int i = blockIdx.x;
    const int V = hn[b] + on[b];
    const int t = threadIdx.x;
    float a0 = 0.f, a1 = 0.f, a2 = 0.f, a3 = 0.f;
    if (i < V) {
        const float* sp = g_sA + (b * NN + i) * NN;   // s2 in g_sA after pass 2
        const float* mp = g_mraw + (size_t)(b * NN + i) * NN * MD;
        int w = 0;
        for (; w + 3 < V; w += 4) {
            float g0 = sigmoidf_(sp[w]);
            float g1 = sigmoidf_(sp[w + 1]);
            float g2 = sigmoidf_(sp[w + 2]);
            float g3 = sigmoidf_(sp[w + 3]);
            a0 = fmaf(g0, mp[(size_t)w * MD + t], a0);
            a1 = fmaf(g1, mp[(size_t)(w + 1) * MD + t], a1);
            a2 = fmaf(g2, mp[(size_t)(w + 2) * MD + t], a2);
            a3 = fmaf(g3, mp[(size_t)(w + 3) * MD + t], a3);
        }
        for (; w < V; w++) {
            float g0 = sigmoidf_(sp[w]);
            a0 = fmaf(g0, mp[(size_t)w * MD + t], a0);
        }
    }
    g_msum[(size_t)(b * NN + i) * MD + t] = (a0 + a1) + (a2 + a3);
}

// ---------------- GRU + readout, 4 nodes per block ----------------
__global__ __launch_bounds__(128) void k_gru(
    const int* __restrict__ hn, const int* __restrict__ on,
    const float* __restrict__ W_ih, const float* __restrict__ b_ih,
    const float* __restrict__ W_hh, const float* __restrict__ b_hh,
    const float* __restrict__ W_ro, const float* __restrict__ b_ro,
    float* __restrict__ out)
{
    const int b  = blockIdx.y;
    const int V  = hn[b] + on[b];
    const int i0 = blockIdx.x * 4;
    const int t  = threadIdx.x;

    __shared__ float ms[4][MD];
    __shared__ float hsn[4][MD];
    __shared__ float hnew[4][MD];

    #pragma unroll
    for (int n = 0; n < 4; n++) {
        ms[n][t]  = g_msum[(size_t)(b * NN + i0 + n) * MD + t];
        hsn[n][t] = g_nf[(size_t)(b * NN + i0 + n) * MD + t];
    }
    __syncthreads();

    float air[4], aiz[4], ain[4], ahr[4], ahz[4], ahn[4];
    {
        float bir = b_ih[t], biz = b_ih[128 + t], bin_ = b_ih[256 + t];
        float bhr = b_hh[t], bhz = b_hh[128 + t], bhn = b_hh[256 + t];
        #pragma unroll
        for (int n = 0; n < 4; n++) {
            air[n] = bir; aiz[n] = biz; ain[n] = bin_;
            ahr[n] = bhr; ahz[n] = bhz; ahn[n] = bhn;
        }
    }
    #pragma unroll 2
    for (int k = 0; k < MD; k++) {
        float wr = W_ih[k * 384 + t];
        float wz = W_ih[k * 384 + 128 + t];
        float wn = W_ih[k * 384 + 256 + t];
        float vr = W_hh[k * 384 + t];
        float vz = W_hh[k * 384 + 128 + t];
        float vn = W_hh[k * 384 + 256 + t];
        #pragma unroll
        for (int n = 0; n < 4; n++) {
            float xv = ms[n][k], hv = hsn[n][k];
            air[n] = fmaf(xv, wr, air[n]);
            aiz[n] = fmaf(xv, wz, aiz[n]);
            ain[n] = fmaf(xv, wn, ain[n]);
            ahr[n] = fmaf(hv, vr, ahr[n]);
            ahz[n] = fmaf(hv, vz, ahz[n]);
            ahn[n] = fmaf(hv, vn, ahn[n]);
        }
    }
    #pragma unroll
    for (int n = 0; n < 4; n++) {
        float r   = sigmoidf_(air[n] + ahr[n]);
        float z   = sigmoidf_(aiz[n] + ahz[n]);
        float nn_ = tanhf(ain[n] + r * ahn[n]);
        hnew[n][t] = (1.f - z) * nn_ + z * hsn[n][t];
    }
    __syncthreads();

    float* lab = out + (size_t)BN * NN * NN;
    for (int cb = 0; cb < 5; cb++) {
        int c = cb * 128 + t;
        if (c >= CLS) continue;
        float lacc[4];
        #pragma unroll
        for (int n = 0; n < 4; n++) lacc[n] = 0.f;
        #pragma unroll 4
        for (int k = 0; k < MD; k++) {
            float wv = W_ro[k * CLS + c];
            #pragma unroll
            for (int n = 0; n < 4; n++) lacc[n] = fmaf(hnew[n][k], wv, lacc[n]);
        }
        float bv = b_ro[c];
        #pragma unroll
        for (int n = 0; n < 4; n++) {
            int i = i0 + n;
            float v = (i < V) ? (lacc[n] + bv) : 0.f;
            lab[(size_t)(b * NN + i) * CLS + c] = v;
        }
    }
}

// ---------------- launcher ----------------
extern "C" void kernel_launch(void* const* d_in, const int* in_sizes, int n_in,
                              void* d_out, int out_size)
{
    const float* edge_features = (const float*)d_in[0];
    const float* node_features = (const float*)d_in[1];
    const int*   human = (const int*)d_in[4];
    const int*   obj   = (const int*)d_in[5];
    const float* W_er  = (const float*)d_in[6];
    const float* b_er  = (const float*)d_in[7];
    const float* W_nr  = (const float*)d_in[8];
    const float* b_nr  = (const float*)d_in[9];
    const float* W_l1  = (const float*)d_in[10];
    const float* b_l1  = (const float*)d_in[11];
    const float* W_l2  = (const float*)d_in[12];
    const float* b_l2  = (const float*)d_in[13];
    const float* W_msg = (const float*)d_in[14];
    const float* b_msg = (const float*)d_in[15];
    const float* W_ih  = (const float*)d_in[16];
    const float* b_ih  = (const float*)d_in[17];
    const float* W_hh  = (const float*)d_in[18];
    const float* b_hh  = (const float*)d_in[19];
    const float* W_ro  = (const float*)d_in[20];
    const float* b_ro  = (const float*)d_in[21];
    float* out = (float*)d_out;

    k_prep<<<1025, 128>>>(out, node_features, W_er, b_er, W_nr, b_nr, W_msg, b_msg, W_l1, b_l1);

    dim3 eg(NN / 16, NN / 4, BN);    // 16 x 64 x 4 = 4096 CTAs, 64 edges each
    k_edge_mma<<<eg, 256>>>(edge_features, human, obj, W_l2, b_l2);
    k_round_mma<<<eg, 256>>>(1, human, obj, b_l1, W_l2, b_l2, nullptr);
    k_round_mma<<<eg, 256>>>(2, human, obj, b_l1, W_l2, b_l2, out);

    k_msum<<<dim3(NN, BN), 128>>>(human, obj);
    k_gru<<<dim3(NN / 4, BN), 128>>>(human, obj, W_ih, b_ih, W_hh, b_hh, W_ro, b_ro, out);
}

// round 7
// speedup vs baseline: 1.0405x; 1.0405x over previous
#include <cuda_runtime.h>
#include <math.h>
#include <stdint.h>

#define BN 4
#define NN 256
#define EFD 256
#define MD 128
#define CLS 600

// ---------------- device scratch (static, zero-init) ----------------
__device__ float g_mraw[(size_t)BN * NN * NN * MD];   // 128 MB
__device__ float g_sA[BN * NN * NN];
__device__ float g_sB[BN * NN * NN];
__device__ float g_nf[BN * NN * MD];
__device__ float g_anf[BN * NN * MD];
__device__ float g_msum[BN * NN * MD];
__device__ float g_Wem[EFD * MD];   // tf32(W_er @ W_msg_bot), row-major [k][c]
__device__ float g_Wel[EFD * MD];   // tf32(W_er @ W_l1)
__device__ float g_Wl1c[MD * MD];   // tf32(W_l1)
__device__ float g_bem[MD];         // b_er @ W_msg_bot
__device__ float g_bel[MD];         // b_er @ W_l1 + b_l1

__device__ __forceinline__ float sigmoidf_(float x) { return 1.0f / (1.0f + __expf(-x)); }

__device__ __forceinline__ float tf32f(float v) {
    uint32_t u;
    asm("cvt.rna.tf32.f32 %0, %1;" : "=r"(u) : "f"(v));
    return __uint_as_float(u);
}

__device__ __forceinline__ void mma8(float* c, const uint32_t* a, const uint32_t* b) {
    asm volatile(
        "mma.sync.aligned.m16n8k8.row.col.f32.tf32.tf32.f32 "
        "{%0,%1,%2,%3}, {%4,%5,%6,%7}, {%8,%9}, {%0,%1,%2,%3};"
        : "+f"(c[0]), "+f"(c[1]), "+f"(c[2]), "+f"(c[3])
        : "r"(a[0]), "r"(a[1]), "r"(a[2]), "r"(a[3]), "r"(b[0]), "r"(b[1]));
}

__device__ __forceinline__ uint32_t smem_u32(const void* p) {
    uint32_t a;
    asm("{ .reg .u64 t; cvta.to.shared.u64 t, %1; cvt.u32.u64 %0, t; }" : "=r"(a) : "l"(p));
    return a;
}
__device__ __forceinline__ void cpa16(uint32_t dst, const float* src) {
    asm volatile("cp.async.cg.shared.global [%0], [%1], 16;" :: "r"(dst), "l"(src));
}
#define CPA_COMMIT() asm volatile("cp.async.commit_group;" ::: "memory")
#define CPA_WAIT0()  asm volatile("cp.async.wait_group 0;" ::: "memory")

// ================= prep: zero adj + fold weights + node features =================
// 256 threads. blocks: [0,256) zero, [256,513) fold, [513,769) nodes (4 nodes each).
// fold/nodes use 2-way K-split across thread halves + smem combine.
__global__ __launch_bounds__(256) void k_prep(
    float* __restrict__ out,
    const float* __restrict__ nfeat,
    const float* __restrict__ W_er, const float* __restrict__ b_er,
    const float* __restrict__ W_nr, const float* __restrict__ b_nr,
    const float* __restrict__ W_msg, const float* __restrict__ b_msg,
    const float* __restrict__ W_l1, const float* __restrict__ b_l1)
{
    const int t = threadIdx.x;
    const int blk = blockIdx.x;
    __shared__ float xs[4][EFD];           // 4 KB
    __shared__ float nfs[4][MD];           // 2 KB
    __shared__ float part[2][4][MD];       // 4 KB

    if (blk < 256) {                       // zero pred_adj region (1 MB)
        int idx = blk * 256 + t;
        reinterpret_cast<float4*>(out)[idx] = make_float4(0.f, 0.f, 0.f, 0.f);
    } else if (blk < 513) {                // fold, k-split across halves
        const int k = blk - 256;           // 0..256
        const int c = t & 127;
        const int h = t >> 7;
        float am = 0.f, al = 0.f;
        if (k < EFD) {
            #pragma unroll 8
            for (int j = h * 64; j < h * 64 + 64; j++) {
                float a = W_er[k * MD + j];
                am = fmaf(a, W_msg[(MD + j) * MD + c], am);
                al = fmaf(a, W_l1[j * MD + c], al);
            }
        } else {
            #pragma unroll 8
            for (int j = h * 64; j < h * 64 + 64; j++) {
                float a = b_er[j];
                am = fmaf(a, W_msg[(MD + j) * MD + c], am);
                al = fmaf(a, W_l1[j * MD + c], al);
            }
        }
        part[h][0][c] = am;
        part[h][1][c] = al;
        __syncthreads();
        if (h == 0) {
            float amt = part[0][0][c] + part[1][0][c];
            float alt = part[0][1][c] + part[1][1][c];
            if (k < EFD) {
                g_Wem[k * MD + c] = tf32f(amt);
                g_Wel[k * MD + c] = tf32f(alt);
                if (k < MD) g_Wl1c[k * MD + c] = tf32f(W_l1[k * MD + c]);
            } else {
                g_bem[c] = amt;
                g_bel[c] = alt + b_l1[c];
            }
        }
    } else {                               // node features: 4 nodes, k-split halves
        const int g0 = (blk - 513) * 4;
        const int c = t & 127;
        const int h = t >> 7;
        {
            const float4* src = reinterpret_cast<const float4*>(nfeat + (size_t)g0 * EFD);
            reinterpret_cast<float4*>(&xs[0][0])[t] = src[t];   // 256 float4 = 4x256 floats
        }
        __syncthreads();
        float acc[4] = {0.f, 0.f, 0.f, 0.f};
        #pragma unroll 8
        for (int k = h * 128; k < h * 128 + 128; k++) {
            float wv = W_nr[k * MD + c];
            #pragma unroll
            for (int n = 0; n < 4; n++) acc[n] = fmaf(xs[n][k], wv, acc[n]);
        }
        #pragma unroll
        for (int n = 0; n < 4; n++) part[h][n][c] = acc[n];
        __syncthreads();
        if (h == 0) {
            float bv = b_nr[c];
            #pragma unroll
            for (int n = 0; n < 4; n++) {
                float v = part[0][n][c] + part[1][n][c] + bv;
                nfs[n][c] = v;
                g_nf[(size_t)(g0 + n) * MD + c] = v;
            }
        }
        __syncthreads();
        float acc2[4] = {0.f, 0.f, 0.f, 0.f};
        #pragma unroll 8
        for (int k = h * 64; k < h * 64 + 64; k++) {
            float wv = W_msg[k * MD + c];   // top half rows of W_msg
            #pragma unroll
            for (int n = 0; n < 4; n++) acc2[n] = fmaf(nfs[n][k], wv, acc2[n]);
        }
        #pragma unroll
        for (int n = 0; n < 4; n++) part[h][n][c] = acc2[n];
        __syncthreads();
        if (h == 0) {
            float bv = b_msg[c];
            #pragma unroll
            for (int n = 0; n < 4; n++)
                g_anf[(size_t)(g0 + n) * MD + c] = part[0][n][c] + part[1][n][c] + bv;
        }
    }
}

// ================= edge kernel: tf32 mma.sync (R5 structure) =================
// CTA: 64 edges (4 recv x 16 send) x N=256 (cols 0-127: W_em path, 128-255: W_el path).
// 256 threads, 8 warps: mg = wid>>2 (rows mg*32..+31), ng = wid&3 (cols ng*64..+63).
// K = 256 in 8 chunks of 32.
#define AP 36      // A smem pitch
#define BP 264     // B smem pitch
__global__ __launch_bounds__(256, 2) void k_edge_mma(
    const float* __restrict__ X,
    const int* __restrict__ hn, const int* __restrict__ on,
    const float* __restrict__ W_l2, const float* __restrict__ b_l2)
{
    const int b  = blockIdx.z;
    const int V  = hn[b] + on[b];
    const int i0 = blockIdx.y * 4;
    const int w0 = blockIdx.x * 16;
    if (i0 >= V || w0 >= V) return;

    __shared__ float As[64][AP];           // 9.2 KB
    __shared__ float Bs[32][BP];           // 33.8 KB (reused as mstage[64][132])
    __shared__ float lpart[2][64];
    __shared__ float bem_s[MD], bel_s[MD], u_s[MD];

    const int t    = threadIdx.x;
    const int wid  = t >> 5;
    const int lane = t & 31;
    const int g    = lane >> 2;
    const int l    = lane & 3;
    const int mg   = wid >> 2;             // 0..1
    const int ng   = wid & 3;              // 0..3

    if (t < 128) { bem_s[t] = g_bem[t]; bel_s[t] = g_bel[t]; u_s[t] = W_l2[t]; }

    const int arow  = t >> 2;              // 0..63 (A fill row)
    const int apart = t & 3;
    const int ari = arow >> 4, awi = arow & 15;
    const float* xrow = X + (size_t)((b * NN + i0 + ari) * NN + w0 + awi) * EFD + apart * 8;

    float acc[2][8][4];
    #pragma unroll
    for (int m = 0; m < 2; m++)
        #pragma unroll
        for (int n = 0; n < 8; n++)
            #pragma unroll
            for (int q = 0; q < 4; q++) acc[m][n][q] = 0.f;

    #pragma unroll 1
    for (int kc = 0; kc < 8; kc++) {
        // A tile: 64 x 32 (tf32-rounded)
        #pragma unroll
        for (int jj = 0; jj < 2; jj++) {
            float4 v = *(const float4*)(xrow + kc * 32 + jj * 4);
            float4 w = make_float4(tf32f(v.x), tf32f(v.y), tf32f(v.z), tf32f(v.w));
            *(float4*)(&As[arow][apart * 8 + jj * 4]) = w;
        }
        // B tile: 32 x 256 (pre-converted)
        #pragma unroll
        for (int jj = 0; jj < 8; jj++) {
            int idx = jj * 256 + t;        // 0..2047 float4s
            int row = idx >> 6;            // 0..31
            int c4  = idx & 63;            // 0..63
            const float* src = (c4 < 32)
                ? &g_Wem[(size_t)(kc * 32 + row) * MD + c4 * 4]
                : &g_Wel[(size_t)(kc * 32 + row) * MD + (c4 - 32) * 4];
            *(float4*)(&Bs[row][c4 * 4]) = *(const float4*)src;
        }
        __syncthreads();
        #pragma unroll
        for (int kb = 0; kb < 32; kb += 8) {
            uint32_t af[2][4];
            #pragma unroll
            for (int m = 0; m < 2; m++) {
                int r0 = mg * 32 + m * 16;
                af[m][0] = __float_as_uint(As[r0 + g][kb + l]);
                af[m][1] = __float_as_uint(As[r0 + g + 8][kb + l]);
                af[m][2] = __float_as_uint(As[r0 + g][kb + l + 4]);
                af[m][3] = __float_as_uint(As[r0 + g + 8][kb + l + 4]);
            }
            #pragma unroll
            for (int n = 0; n < 8; n++) {
                uint32_t bf[2];
                int nb = ng * 64 + n * 8 + g;
                bf[0] = __float_as_uint(Bs[kb + l][nb]);
                bf[1] = __float_as_uint(Bs[kb + l + 4][nb]);
                mma8(acc[0][n], af[0], bf);
                mma8(acc[1][n], af[1], bf);
            }
        }
        __syncthreads();
    }

    const float bl2v = b_l2[0];
    if (ng >= 2) {
        // ---- link path: p[row] = sum_c relu(acc + bel[c]) * u[c] ----
        float p[4] = {0.f, 0.f, 0.f, 0.f};
        #pragma unroll
        for (int m = 0; m < 2; m++)
            #pragma unroll
            for (int n = 0; n < 8; n++) {
                int cb = (ng - 2) * 64 + n * 8 + 2 * l;
                float u0 = u_s[cb], u1 = u_s[cb + 1];
                float e0 = bel_s[cb], e1 = bel_s[cb + 1];
                p[m*2+0] += fmaxf(acc[m][n][0] + e0, 0.f) * u0 + fmaxf(acc[m][n][1] + e1, 0.f) * u1;
                p[m*2+1] += fmaxf(acc[m][n][2] + e0, 0.f) * u0 + fmaxf(acc[m][n][3] + e1, 0.f) * u1;
            }
        #pragma unroll
        for (int q = 0; q < 4; q++) {
            p[q] += __shfl_xor_sync(0xffffffffu, p[q], 1);
            p[q] += __shfl_xor_sync(0xffffffffu, p[q], 2);
        }
        if (l == 0) {
            lpart[ng - 2][mg * 32 + g]      = p[0];
            lpart[ng - 2][mg * 32 + g + 8]  = p[1];
            lpart[ng - 2][mg * 32 + 16 + g] = p[2];
            lpart[ng - 2][mg * 32 + 24 + g] = p[3];
        }
    } else {
        // ---- message path: stage raw accs ----
        float* mst = &Bs[0][0];            // [64][132]
        #pragma unroll
        for (int m = 0; m < 2; m++) {
            int r0 = mg * 32 + m * 16 + g;
            #pragma unroll
            for (int n = 0; n < 8; n++) {
                int cb = ng * 64 + n * 8 + 2 * l;
                mst[r0 * 132 + cb]           = acc[m][n][0];
                mst[r0 * 132 + cb + 1]       = acc[m][n][1];
                mst[(r0 + 8) * 132 + cb]     = acc[m][n][2];
                mst[(r0 + 8) * 132 + cb + 1] = acc[m][n][3];
            }
        }
    }
    __syncthreads();

    if (t < 64) {
        int ri2 = t >> 4, wi2 = t & 15;
        if (i0 + ri2 < V && w0 + wi2 < V)
            g_sA[(b * NN + i0 + ri2) * NN + w0 + wi2] = lpart[0][t] + lpart[1][t] + bl2v;
    }
    {
        int row = t >> 2, part = t & 3;
        int ri2 = row >> 4, wi2 = row & 15;
        if (i0 + ri2 < V && w0 + wi2 < V) {
            const float* ap = g_anf + (size_t)(b * NN + w0 + wi2) * MD + part * 32;
            float* mp = g_mraw + (size_t)((b * NN + i0 + ri2) * NN + w0 + wi2) * MD + part * 32;
            const float* mst = &Bs[0][0] + row * 132 + part * 32;
            #pragma unroll
            for (int jj = 0; jj < 8; jj++) {
                float4 m4 = *(const float4*)(mst + jj * 4);
                float4 a4 = *(const float4*)(ap + jj * 4);
                float4 e4 = *(const float4*)(&bem_s[part * 32 + jj * 4]);
                float4 v;
                v.x = fmaxf(m4.x + e4.x + a4.x, 0.f);
                v.y = fmaxf(m4.y + e4.y + a4.y, 0.f);
                v.z = fmaxf(m4.z + e4.z + a4.z, 0.f);
                v.w = fmaxf(m4.w + e4.w + a4.w, 0.f);
                *(float4*)(mp + jj * 4) = v;
            }
        }
    }
}

// ================= round kernel: R5 chunked structure + cp.async pipeline =================
// s_next[i,w] = relu( (sig(s_prev[w,i])*m_raw[w,i]) @ W_l1 + b_l1 ) . W_l2 + b_l2
// CTA: 64 edges x N=128, K=128 in 4 chunks of 32, A+B double-buffered.
#define RBP 136
__global__ __launch_bounds__(256, 2) void k_round_mma(
    int pass,
    const int* __restrict__ hn, const int* __restrict__ on,
    const float* __restrict__ b_l1,
    const float* __restrict__ W_l2, const float* __restrict__ b_l2,
    float* __restrict__ out_adj)
{
    const int b  = blockIdx.z;
    const int V  = hn[b] + on[b];
    const int i0 = blockIdx.y * 4;
    const int w0 = blockIdx.x * 16;
    if (i0 >= V || w0 >= V) return;

    const float* sprev = (pass == 1) ? g_sA : g_sB;
    float*       snext = (pass == 1) ? g_sB : g_sA;

    __shared__ float As[2][64][AP];        // 18.4 KB
    __shared__ float Bs[2][32][RBP];       // 34.8 KB
    __shared__ float lpart[4][64];
    __shared__ float gates[64];
    __shared__ float bl1_s[MD], u_s[MD];

    const int t    = threadIdx.x;
    const int wid  = t >> 5;
    const int lane = t & 31;
    const int g    = lane >> 2;
    const int l    = lane & 3;
    const int mg   = wid >> 2;
    const int ng   = wid & 3;

    if (t < 128) { bl1_s[t] = b_l1[t]; u_s[t] = W_l2[t]; }
    if (t < 64) {
        int ri = t >> 4, wi = t & 15;
        bool ok = (i0 + ri < V) && (w0 + wi < V);
        gates[t] = ok ? sigmoidf_(sprev[(b * NN + w0 + wi) * NN + i0 + ri]) : 0.f;
    }
    __syncthreads();

    const int arow  = t >> 2;
    const int apart = t & 3;
    const int ari = arow >> 4, awi = arow & 15;
    const float gv = gates[arow];
    const float* mrow = g_mraw + (size_t)((b * NN + w0 + awi) * NN + i0 + ari) * MD + apart * 8;

    // B cp.async targets: 1024 float4 per chunk / 256 threads = 4 each
    uint32_t bdst[4];
    const float* bsrc[4];
    #pragma unroll
    for (int jj = 0; jj < 4; jj++) {
        int idx = jj * 256 + t;            // 0..1023
        int row = idx >> 5;                // 0..31
        int c4  = idx & 31;
        bdst[jj] = smem_u32(&Bs[0][row][c4 * 4]);
        bsrc[jj] = &g_Wl1c[(size_t)row * MD + c4 * 4];
    }
    const uint32_t bufB = (uint32_t)(32 * RBP * 4);

    float acc[2][4][4];
    #pragma unroll
    for (int m = 0; m < 2; m++)
        #pragma unroll
        for (int n = 0; n < 4; n++)
            #pragma unroll
            for (int q = 0; q < 4; q++) acc[m][n][q] = 0.f;

    float ar[8];
    // prologue: chunk 0
    #pragma unroll
    for (int jj = 0; jj < 8; jj++) ar[jj] = mrow[jj];
    #pragma unroll
    for (int jj = 0; jj < 4; jj++) cpa16(bdst[jj], bsrc[jj]);
    CPA_COMMIT();
    #pragma unroll
    for (int jj = 0; jj < 8; jj++) As[0][arow][apart * 8 + jj] = tf32f(ar[jj] * gv);
    CPA_WAIT0();
    __syncthreads();

    #pragma unroll 1
    for (int kc = 0; kc < 4; kc++) {
        const int cur = kc & 1, nxt = cur ^ 1;
        if (kc < 3) {
            #pragma unroll
            for (int jj = 0; jj < 4; jj++)
                cpa16(bdst[jj] + nxt * bufB, bsrc[jj] + (size_t)(kc + 1) * 32 * MD);
            CPA_COMMIT();
            #pragma unroll
            for (int jj = 0; jj < 8; jj++) ar[jj] = mrow[(kc + 1) * 32 + jj];
        }
        #pragma unroll
        for (int kb = 0; kb < 32; kb += 8) {
            uint32_t af[2][4];
            #pragma unroll
            for (int m = 0; m < 2; m++) {
                int r0 = mg * 32 + m * 16;
                af[m][0] = __float_as_uint(As[cur][r0 + g][kb + l]);
                af[m][1] = __float_as_uint(As[cur][r0 + g + 8][kb + l]);
                af[m][2] = __float_as_uint(As[cur][r0 + g][kb + l + 4]);
                af[m][3] = __float_as_uint(As[cur][r0 + g + 8][kb + l + 4]);
            }
            #pragma unroll
            for (int n = 0; n < 4; n++) {
                uint32_t bf[2];
                int nb = ng * 32 + n * 8 + g;
                bf[0] = __float_as_uint(Bs[cur][kb + l][nb]);
                bf[1] = __float_as_uint(Bs[cur][kb + l + 4][nb]);
                mma8(acc[0][n], af[0], bf);
                mma8(acc[1][n], af[1], bf);
            }
        }
        if (kc < 3) {
            #pragma unroll
            for (int jj = 0; jj < 8; jj++) As[nxt][arow][apart * 8 + jj] = tf32f(ar[jj] * gv);
            CPA_WAIT0();
        }
        __syncthreads();
    }

    // link reduction: each warp owns 32 cols
    {
        float p[4] = {0.f, 0.f, 0.f, 0.f};
        #pragma unroll
        for (int m = 0; m < 2; m++)
            #pragma unroll
            for (int n = 0; n < 4; n++) {
                int cb = ng * 32 + n * 8 + 2 * l;
                float u0 = u_s[cb], u1 = u_s[cb + 1];
                float e0 = bl1_s[cb], e1 = bl1_s[cb + 1];
                p[m*2+0] += fmaxf(acc[m][n][0] + e0, 0.f) * u0 + fmaxf(acc[m][n][1] + e1, 0.f) * u1;
                p[m*2+1] += fmaxf(acc[m][n][2] + e0, 0.f) * u0 + fmaxf(acc[m][n][3] + e1, 0.f) * u1;
            }
        #pragma unroll
        for (int q = 0; q < 4; q++) {
            p[q] += __shfl_xor_sync(0xffffffffu, p[q], 1);
            p[q] += __shfl_xor_sync(0xffffffffu, p[q], 2);
        }
        if (l == 0) {
            lpart[ng][mg * 32 + g]      = p[0];
            lpart[ng][mg * 32 + g + 8]  = p[1];
            lpart[ng][mg * 32 + 16 + g] = p[2];
            lpart[ng][mg * 32 + 24 + g] = p[3];
        }
    }
    __syncthreads();
    if (t < 64) {
        int ri2 = t >> 4, wi2 = t & 15;
        if (i0 + ri2 < V && w0 + wi2 < V) {
            int d = (b * NN + i0 + ri2) * NN + w0 + wi2;
            float sv = (lpart[0][t] + lpart[1][t]) + (lpart[2][t] + lpart[3][t]) + b_l2[0];
            snext[d] = sv;
            if (out_adj) out_adj[d] = sv;
        }
    }
}

// ---------------- m_sum[b,i] = sum_w sigmoid(s2[i,w]) * m_raw[i,w,:] ----------------
__global__ __launch_bounds__(128) void k_msum(const int* __restrict__ hn, const int* __restrict__ on) {
    const int b = blockIdx.y;
    const int i = blockIdx.x;
    const int V = hn[b] + on[b];
    const int t = threadIdx.x;
    float a[8];
    #pragma unroll
    for (int q = 0; q < 8; q++) a[q] = 0.f;
    if (i < V) {
        const float* sp = g_sA + (b * NN + i) * NN;   // s2 in g_sA after pass 2
        const float* mp = g_mraw + (size_t)(b * NN + i) * NN * MD;
        int w = 0;
        for (; w + 7 < V; w += 8) {
            #pragma unroll
            for (int q = 0; q < 8; q++) {
                float gq = sigmoidf_(sp[w + q]);
                a[q] = fmaf(gq, mp[(size_t)(w + q) * MD + t], a[q]);
            }
        }
        for (; w < V; w++) {
            float gq = sigmoidf_(sp[w]);
            a[0] = fmaf(gq, mp[(size_t)w * MD + t], a[0]);
        }
    }
    g_msum[(size_t)(b * NN + i) * MD + t] =
        ((a[0] + a[1]) + (a[2] + a[3])) + ((a[4] + a[5]) + (a[6] + a[7]));
}

// ---------------- GRU + readout, 4 nodes per block ----------------
__global__ __launch_bounds__(128) void k_gru(
    const int* __restrict__ hn, const int* __restrict__ on,
    const float* __restrict__ W_ih, const float* __restrict__ b_ih,
    const float* __restrict__ W_hh, const float* __restrict__ b_hh,
    const float* __restrict__ W_ro, const float* __restrict__ b_ro,
    float* __restrict__ out)
{
    const int b  = blockIdx.y;
    const int V  = hn[b] + on[b];
    const int i0 = blockIdx.x * 4;
    const int t  = threadIdx.x;

    __shared__ float ms[4][MD];
    __shared__ float hsn[4][MD];
    __shared__ float hnew[4][MD];

    #pragma unroll
    for (int n = 0; n < 4; n++) {
        ms[n][t]  = g_msum[(size_t)(b * NN + i0 + n) * MD + t];
        hsn[n][t] = g_nf[(size_t)(b * NN + i0 + n) * MD + t];
    }
    __syncthreads();

    float air[4], aiz[4], ain[4], ahr[4], ahz[4], ahn[4];
    {
        float bir = b_ih[t], biz = b_ih[128 + t], bin_ = b_ih[256 + t];
        float bhr = b_hh[t], bhz = b_hh[128 + t], bhn = b_hh[256 + t];
        #pragma unroll
        for (int n = 0; n < 4; n++) {
            air[n] = bir; aiz[n] = biz; ain[n] = bin_;
            ahr[n] = bhr; ahz[n] = bhz; ahn[n] = bhn;
        }
    }
    #pragma unroll 2
    for (int k = 0; k < MD; k++) {
        float wr = W_ih[k * 384 + t];
        float wz = W_ih[k * 384 + 128 + t];
        float wn = W_ih[k * 384 + 256 + t];
        float vr = W_hh[k * 384 + t];
        float vz = W_hh[k * 384 + 128 + t];
        float vn = W_hh[k * 384 + 256 + t];
        #pragma unroll
        for (int n = 0; n < 4; n++) {
            float xv = ms[n][k], hv = hsn[n][k];
            air[n] = fmaf(xv, wr, air[n]);
            aiz[n] = fmaf(xv, wz, aiz[n]);
            ain[n] = fmaf(xv, wn, ain[n]);
            ahr[n] = fmaf(hv, vr, ahr[n]);
            ahz[n] = fmaf(hv, vz, ahz[n]);
            ahn[n] = fmaf(hv, vn, ahn[n]);
        }
    }
    #pragma unroll
    for (int n = 0; n < 4; n++) {
        float r   = sigmoidf_(air[n] + ahr[n]);
        float z   = sigmoidf_(aiz[n] + ahz[n]);
        float nn_ = tanhf(ain[n] + r * ahn[n]);
        hnew[n][t] = (1.f - z) * nn_ + z * hsn[n][t];
    }
    __syncthreads();

    float* lab = out + (size_t)BN * NN * NN;
    for (int cb = 0; cb < 5; cb++) {
        int c = cb * 128 + t;
        if (c >= CLS) continue;
        float lacc[4];
        #pragma unroll
        for (int n = 0; n < 4; n++) lacc[n] = 0.f;
        #pragma unroll 4
        for (int k = 0; k < MD; k++) {
            float wv = W_ro[k * CLS + c];
            #pragma unroll
            for (int n = 0; n < 4; n++) lacc[n] = fmaf(hnew[n][k], wv, lacc[n]);
        }
        float bv = b_ro[c];
        #pragma unroll
        for (int n = 0; n < 4; n++) {
            int i = i0 + n;
            float v = (i < V) ? (lacc[n] + bv) : 0.f;
            lab[(size_t)(b * NN + i) * CLS + c] = v;
        }
    }
}

// ---------------- launcher ----------------
extern "C" void kernel_launch(void* const* d_in, const int* in_sizes, int n_in,
                              void* d_out, int out_size)
{
    const float* edge_features = (const float*)d_in[0];
    const float* node_features = (const float*)d_in[1];
    const int*   human = (const int*)d_in[4];
    const int*   obj   = (const int*)d_in[5];
    const float* W_er  = (const float*)d_in[6];
    const float* b_er  = (const float*)d_in[7];
    const float* W_nr  = (const float*)d_in[8];
    const float* b_nr  = (const float*)d_in[9];
    const float* W_l1  = (const float*)d_in[10];
    const float* b_l1  = (const float*)d_in[11];
    const float* W_l2  = (const float*)d_in[12];
    const float* b_l2  = (const float*)d_in[13];
    const float* W_msg = (const float*)d_in[14];
    const float* b_msg = (const float*)d_in[15];
    const float* W_ih  = (const float*)d_in[16];
    const float* b_ih  = (const float*)d_in[17];
    const float* W_hh  = (const float*)d_in[18];
    const float* b_hh  = (const float*)d_in[19];
    const float* W_ro  = (const float*)d_in[20];
    const float* b_ro  = (const float*)d_in[21];
    float* out = (float*)d_out;

    k_prep<<<769, 256>>>(out, node_features, W_er, b_er, W_nr, b_nr, W_msg, b_msg, W_l1, b_l1);

    dim3 eg(NN / 16, NN / 4, BN);    // 16 x 64 x 4 = 4096 CTAs, 64 edges each
    k_edge_mma<<<eg, 256>>>(edge_features, human, obj, W_l2, b_l2);
    k_round_mma<<<eg, 256>>>(1, human, obj, b_l1, W_l2, b_l2, nullptr);
    k_round_mma<<<eg, 256>>>(2, human, obj, b_l1, W_l2, b_l2, out);

    k_msum<<<dim3(NN, BN), 128>>>(human, obj);
    k_gru<<<dim3(NN / 4, BN), 128>>>(human, obj, W_ih, b_ih, W_hh, b_hh, W_ro, b_ro, out);
}

// round 8
// speedup vs baseline: 1.1913x; 1.1449x over previous
#include <cuda_runtime.h>
#include <math.h>
#include <stdint.h>

#define BN 4
#define NN 256
#define EFD 256
#define MD 128
#define CLS 600

// ---------------- device scratch (static, zero-init) ----------------
__device__ float g_mraw[(size_t)BN * NN * NN * MD];   // 128 MB
__device__ float g_sA[BN * NN * NN];
__device__ float g_sB[BN * NN * NN];
__device__ float g_nf[BN * NN * MD];
__device__ float g_anf[BN * NN * MD];
__device__ float g_msum[BN * NN * MD];
__device__ float g_Wem[EFD * MD];   // tf32(W_er @ W_msg_bot), row-major [k][c]
__device__ float g_Wel[EFD * MD];   // tf32(W_er @ W_l1)
__device__ float g_Wl1c[MD * MD];   // tf32(W_l1)
__device__ float g_bem[MD];         // b_er @ W_msg_bot
__device__ float g_bel[MD];         // b_er @ W_l1 + b_l1

__device__ __forceinline__ float sigmoidf_(float x) { return 1.0f / (1.0f + __expf(-x)); }

__device__ __forceinline__ float tf32f(float v) {
    uint32_t u;
    asm("cvt.rna.tf32.f32 %0, %1;" : "=r"(u) : "f"(v));
    return __uint_as_float(u);
}

__device__ __forceinline__ void mma8(float* c, const uint32_t* a, const uint32_t* b) {
    asm volatile(
        "mma.sync.aligned.m16n8k8.row.col.f32.tf32.tf32.f32 "
        "{%0,%1,%2,%3}, {%4,%5,%6,%7}, {%8,%9}, {%0,%1,%2,%3};"
        : "+f"(c[0]), "+f"(c[1]), "+f"(c[2]), "+f"(c[3])
        : "r"(a[0]), "r"(a[1]), "r"(a[2]), "r"(a[3]), "r"(b[0]), "r"(b[1]));
}

__device__ __forceinline__ uint32_t smem_u32(const void* p) {
    uint32_t a;
    asm("{ .reg .u64 t; cvta.to.shared.u64 t, %1; cvt.u32.u64 %0, t; }" : "=r"(a) : "l"(p));
    return a;
}
__device__ __forceinline__ void cpa16(uint32_t dst, const float* src) {
    asm volatile("cp.async.cg.shared.global [%0], [%1], 16;" :: "r"(dst), "l"(src));
}
#define CPA_COMMIT() asm volatile("cp.async.commit_group;" ::: "memory")
#define CPA_WAIT0()  asm volatile("cp.async.wait_group 0;" ::: "memory")

// ================= prep: zero adj + zero msum + fold weights + node features =================
// 256 threads. blocks: [0,256) zero adj, [256,384) zero msum,
// [384,641) fold, [641,897) nodes (4 nodes each).
__global__ __launch_bounds__(256) void k_prep(
    float* __restrict__ out,
    const float* __restrict__ nfeat,
    const float* __restrict__ W_er, const float* __restrict__ b_er,
    const float* __restrict__ W_nr, const float* __restrict__ b_nr,
    const float* __restrict__ W_msg, const float* __restrict__ b_msg,
    const float* __restrict__ W_l1, const float* __restrict__ b_l1)
{
    const int t = threadIdx.x;
    const int blk = blockIdx.x;
    __shared__ float xs[4][EFD];           // 4 KB
    __shared__ float nfs[4][MD];           // 2 KB
    __shared__ float part[2][4][MD];       // 4 KB

    if (blk < 256) {                       // zero pred_adj region (1 MB)
        int idx = blk * 256 + t;
        reinterpret_cast<float4*>(out)[idx] = make_float4(0.f, 0.f, 0.f, 0.f);
    } else if (blk < 384) {                // zero g_msum (512 KB)
        int idx = (blk - 256) * 256 + t;
        reinterpret_cast<float4*>(g_msum)[idx] = make_float4(0.f, 0.f, 0.f, 0.f);
    } else if (blk < 641) {                // fold, k-split across halves
        const int k = blk - 384;           // 0..256
        const int c = t & 127;
        const int h = t >> 7;
        float am = 0.f, al = 0.f;
        if (k < EFD) {
            #pragma unroll 8
            for (int j = h * 64; j < h * 64 + 64; j++) {
                float a = W_er[k * MD + j];
                am = fmaf(a, W_msg[(MD + j) * MD + c], am);
                al = fmaf(a, W_l1[j * MD + c], al);
            }
        } else {
            #pragma unroll 8
            for (int j = h * 64; j < h * 64 + 64; j++) {
                float a = b_er[j];
                am = fmaf(a, W_msg[(MD + j) * MD + c], am);
                al = fmaf(a, W_l1[j * MD + c], al);
            }
        }
        part[h][0][c] = am;
        part[h][1][c] = al;
        __syncthreads();
        if (h == 0) {
            float amt = part[0][0][c] + part[1][0][c];
            float alt = part[0][1][c] + part[1][1][c];
            if (k < EFD) {
                g_Wem[k * MD + c] = tf32f(amt);
                g_Wel[k * MD + c] = tf32f(alt);
                if (k < MD) g_Wl1c[k * MD + c] = tf32f(W_l1[k * MD + c]);
            } else {
                g_bem[c] = amt;
                g_bel[c] = alt + b_l1[c];
            }
        }
    } else {                               // node features: 4 nodes, k-split halves
        const int g0 = (blk - 641) * 4;
        const int c = t & 127;
        const int h = t >> 7;
        {
            const float4* src = reinterpret_cast<const float4*>(nfeat + (size_t)g0 * EFD);
            reinterpret_cast<float4*>(&xs[0][0])[t] = src[t];   // 256 float4
        }
        __syncthreads();
        float acc[4] = {0.f, 0.f, 0.f, 0.f};
        #pragma unroll 8
        for (int k = h * 128; k < h * 128 + 128; k++) {
            float wv = W_nr[k * MD + c];
            #pragma unroll
            for (int n = 0; n < 4; n++) acc[n] = fmaf(xs[n][k], wv, acc[n]);
        }
        #pragma unroll
        for (int n = 0; n < 4; n++) part[h][n][c] = acc[n];
        __syncthreads();
        if (h == 0) {
            float bv = b_nr[c];
            #pragma unroll
            for (int n = 0; n < 4; n++) {
                float v = part[0][n][c] + part[1][n][c] + bv;
                nfs[n][c] = v;
                g_nf[(size_t)(g0 + n) * MD + c] = v;
            }
        }
        __syncthreads();
        float acc2[4] = {0.f, 0.f, 0.f, 0.f};
        #pragma unroll 8
        for (int k = h * 64; k < h * 64 + 64; k++) {
            float wv = W_msg[k * MD + c];   // top half rows of W_msg
            #pragma unroll
            for (int n = 0; n < 4; n++) acc2[n] = fmaf(nfs[n][k], wv, acc2[n]);
        }
        #pragma unroll
        for (int n = 0; n < 4; n++) part[h][n][c] = acc2[n];
        __syncthreads();
        if (h == 0) {
            float bv = b_msg[c];
            #pragma unroll
            for (int n = 0; n < 4; n++)
                g_anf[(size_t)(g0 + n) * MD + c] = part[0][n][c] + part[1][n][c] + bv;
        }
    }
}

// ================= edge kernel: tf32 mma.sync (R5 structure, unchanged) =================
#define AP 36      // A smem pitch
#define BP 264     // B smem pitch
__global__ __launch_bounds__(256, 2) void k_edge_mma(
    const float* __restrict__ X,
    const int* __restrict__ hn, const int* __restrict__ on,
    const float* __restrict__ W_l2, const float* __restrict__ b_l2)
{
    const int b  = blockIdx.z;
    const int V  = hn[b] + on[b];
    const int i0 = blockIdx.y * 4;
    const int w0 = blockIdx.x * 16;
    if (i0 >= V || w0 >= V) return;

    __shared__ float As[64][AP];           // 9.2 KB
    __shared__ float Bs[32][BP];           // 33.8 KB (reused as mstage[64][132])
    __shared__ float lpart[2][64];
    __shared__ float bem_s[MD], bel_s[MD], u_s[MD];

    const int t    = threadIdx.x;
    const int wid  = t >> 5;
    const int lane = t & 31;
    const int g    = lane >> 2;
    const int l    = lane & 3;
    const int mg   = wid >> 2;             // 0..1
    const int ng   = wid & 3;              // 0..3

    if (t < 128) { bem_s[t] = g_bem[t]; bel_s[t] = g_bel[t]; u_s[t] = W_l2[t]; }

    const int arow  = t >> 2;              // 0..63 (A fill row)
    const int apart = t & 3;
    const int ari = arow >> 4, awi = arow & 15;
    const float* xrow = X + (size_t)((b * NN + i0 + ari) * NN + w0 + awi) * EFD + apart * 8;

    float acc[2][8][4];
    #pragma unroll
    for (int m = 0; m < 2; m++)
        #pragma unroll
        for (int n = 0; n < 8; n++)
            #pragma unroll
            for (int q = 0; q < 4; q++) acc[m][n][q] = 0.f;

    #pragma unroll 1
    for (int kc = 0; kc < 8; kc++) {
        #pragma unroll
        for (int jj = 0; jj < 2; jj++) {
            float4 v = *(const float4*)(xrow + kc * 32 + jj * 4);
            float4 w = make_float4(tf32f(v.x), tf32f(v.y), tf32f(v.z), tf32f(v.w));
            *(float4*)(&As[arow][apart * 8 + jj * 4]) = w;
        }
        #pragma unroll
        for (int jj = 0; jj < 8; jj++) {
            int idx = jj * 256 + t;        // 0..2047 float4s
            int row = idx >> 6;            // 0..31
            int c4  = idx & 63;            // 0..63
            const float* src = (c4 < 32)
                ? &g_Wem[(size_t)(kc * 32 + row) * MD + c4 * 4]
                : &g_Wel[(size_t)(kc * 32 + row) * MD + (c4 - 32) * 4];
            *(float4*)(&Bs[row][c4 * 4]) = *(const float4*)src;
        }
        __syncthreads();
        #pragma unroll
        for (int kb = 0; kb < 32; kb += 8) {
            uint32_t af[2][4];
            #pragma unroll
            for (int m = 0; m < 2; m++) {
                int r0 = mg * 32 + m * 16;
                af[m][0] = __float_as_uint(As[r0 + g][kb + l]);
                af[m][1] = __float_as_uint(As[r0 + g + 8][kb + l]);
                af[m][2] = __float_as_uint(As[r0 + g][kb + l + 4]);
                af[m][3] = __float_as_uint(As[r0 + g + 8][kb + l + 4]);
            }
            #pragma unroll
            for (int n = 0; n < 8; n++) {
                uint32_t bf[2];
                int nb = ng * 64 + n * 8 + g;
                bf[0] = __float_as_uint(Bs[kb + l][nb]);
                bf[1] = __float_as_uint(Bs[kb + l + 4][nb]);
                mma8(acc[0][n], af[0], bf);
                mma8(acc[1][n], af[1], bf);
            }
        }
        __syncthreads();
    }

    const float bl2v = b_l2[0];
    if (ng >= 2) {
        float p[4] = {0.f, 0.f, 0.f, 0.f};
        #pragma unroll
        for (int m = 0; m < 2; m++)
            #pragma unroll
            for (int n = 0; n < 8; n++) {
                int cb = (ng - 2) * 64 + n * 8 + 2 * l;
                float u0 = u_s[cb], u1 = u_s[cb + 1];
                float e0 = bel_s[cb], e1 = bel_s[cb + 1];
                p[m*2+0] += fmaxf(acc[m][n][0] + e0, 0.f) * u0 + fmaxf(acc[m][n][1] + e1, 0.f) * u1;
                p[m*2+1] += fmaxf(acc[m][n][2] + e0, 0.f) * u0 + fmaxf(acc[m][n][3] + e1, 0.f) * u1;
            }
        #pragma unroll
        for (int q = 0; q < 4; q++) {
            p[q] += __shfl_xor_sync(0xffffffffu, p[q], 1);
            p[q] += __shfl_xor_sync(0xffffffffu, p[q], 2);
        }
        if (l == 0) {
            lpart[ng - 2][mg * 32 + g]      = p[0];
            lpart[ng - 2][mg * 32 + g + 8]  = p[1];
            lpart[ng - 2][mg * 32 + 16 + g] = p[2];
            lpart[ng - 2][mg * 32 + 24 + g] = p[3];
        }
    } else {
        float* mst = &Bs[0][0];            // [64][132]
        #pragma unroll
        for (int m = 0; m < 2; m++) {
            int r0 = mg * 32 + m * 16 + g;
            #pragma unroll
            for (int n = 0; n < 8; n++) {
                int cb = ng * 64 + n * 8 + 2 * l;
                mst[r0 * 132 + cb]           = acc[m][n][0];
                mst[r0 * 132 + cb + 1]       = acc[m][n][1];
                mst[(r0 + 8) * 132 + cb]     = acc[m][n][2];
                mst[(r0 + 8) * 132 + cb + 1] = acc[m][n][3];
            }
        }
    }
    __syncthreads();

    if (t < 64) {
        int ri2 = t >> 4, wi2 = t & 15;
        if (i0 + ri2 < V && w0 + wi2 < V)
            g_sA[(b * NN + i0 + ri2) * NN + w0 + wi2] = lpart[0][t] + lpart[1][t] + bl2v;
    }
    {
        int row = t >> 2, part = t & 3;
        int ri2 = row >> 4, wi2 = row & 15;
        if (i0 + ri2 < V && w0 + wi2 < V) {
            const float* ap = g_anf + (size_t)(b * NN + w0 + wi2) * MD + part * 32;
            float* mp = g_mraw + (size_t)((b * NN + i0 + ri2) * NN + w0 + wi2) * MD + part * 32;
            const float* mst = &Bs[0][0] + row * 132 + part * 32;
            #pragma unroll
            for (int jj = 0; jj < 8; jj++) {
                float4 m4 = *(const float4*)(mst + jj * 4);
                float4 a4 = *(const float4*)(ap + jj * 4);
                float4 e4 = *(const float4*)(&bem_s[part * 32 + jj * 4]);
                float4 v;
                v.x = fmaxf(m4.x + e4.x + a4.x, 0.f);
                v.y = fmaxf(m4.y + e4.y + a4.y, 0.f);
                v.z = fmaxf(m4.z + e4.z + a4.z, 0.f);
                v.w = fmaxf(m4.w + e4.w + a4.w, 0.f);
                *(float4*)(mp + jj * 4) = v;
            }
        }
    }
}

// ================= round kernel: chunked + cp.async, occupancy 3, fused msum on pass 2 =================
#define RBP 136
__global__ __launch_bounds__(256, 3) void k_round_mma(
    int pass,
    const int* __restrict__ hn, const int* __restrict__ on,
    const float* __restrict__ b_l1,
    const float* __restrict__ W_l2, const float* __restrict__ b_l2,
    float* __restrict__ out_adj)
{
    const int b  = blockIdx.z;
    const int V  = hn[b] + on[b];
    const int i0 = blockIdx.y * 4;
    const int w0 = blockIdx.x * 16;
    if (i0 >= V || w0 >= V) return;

    const float* sprev = (pass == 1) ? g_sA : g_sB;
    float*       snext = (pass == 1) ? g_sB : g_sA;

    __shared__ float As[2][64][AP];        // 18.4 KB
    __shared__ float Bs[2][32][RBP];       // 34.8 KB
    __shared__ float lpart[4][64];
    __shared__ float gates[64];            // input gates, then reused for sig(s2)
    __shared__ float bl1_s[MD], u_s[MD];

    const int t    = threadIdx.x;
    const int wid  = t >> 5;
    const int lane = t & 31;
    const int g    = lane >> 2;
    const int l    = lane & 3;
    const int mg   = wid >> 2;
    const int ng   = wid & 3;

    if (t < 128) { bl1_s[t] = b_l1[t]; u_s[t] = W_l2[t]; }
    if (t < 64) {
        int ri = t >> 4, wi = t & 15;
        bool ok = (i0 + ri < V) && (w0 + wi < V);
        gates[t] = ok ? sigmoidf_(sprev[(b * NN + w0 + wi) * NN + i0 + ri]) : 0.f;
    }
    __syncthreads();

    const int arow  = t >> 2;
    const int apart = t & 3;
    const int ari = arow >> 4, awi = arow & 15;
    const float gv = gates[arow];
    const float* mrow = g_mraw + (size_t)((b * NN + w0 + awi) * NN + i0 + ari) * MD + apart * 8;

    uint32_t bdst[4];
    const float* bsrc[4];
    #pragma unroll
    for (int jj = 0; jj < 4; jj++) {
        int idx = jj * 256 + t;            // 0..1023
        int row = idx >> 5;                // 0..31
        int c4  = idx & 31;
        bdst[jj] = smem_u32(&Bs[0][row][c4 * 4]);
        bsrc[jj] = &g_Wl1c[(size_t)row * MD + c4 * 4];
    }
    const uint32_t bufB = (uint32_t)(32 * RBP * 4);

    float acc[2][4][4];
    #pragma unroll
    for (int m = 0; m < 2; m++)
        #pragma unroll
        for (int n = 0; n < 4; n++)
            #pragma unroll
            for (int q = 0; q < 4; q++) acc[m][n][q] = 0.f;

    float ar[8];
    #pragma unroll
    for (int jj = 0; jj < 8; jj++) ar[jj] = mrow[jj];
    #pragma unroll
    for (int jj = 0; jj < 4; jj++) cpa16(bdst[jj], bsrc[jj]);
    CPA_COMMIT();
    #pragma unroll
    for (int jj = 0; jj < 8; jj++) As[0][arow][apart * 8 + jj] = tf32f(ar[jj] * gv);
    CPA_WAIT0();
    __syncthreads();

    #pragma unroll 1
    for (int kc = 0; kc < 4; kc++) {
        const int cur = kc & 1, nxt = cur ^ 1;
        if (kc < 3) {
            #pragma unroll
            for (int jj = 0; jj < 4; jj++)
                cpa16(bdst[jj] + nxt * bufB, bsrc[jj] + (size_t)(kc + 1) * 32 * MD);
            CPA_COMMIT();
            #pragma unroll
            for (int jj = 0; jj < 8; jj++) ar[jj] = mrow[(kc + 1) * 32 + jj];
        }
        #pragma unroll
        for (int kb = 0; kb < 32; kb += 8) {
            uint32_t af[2][4];
            #pragma unroll
            for (int m = 0; m < 2; m++) {
                int r0 = mg * 32 + m * 16;
                af[m][0] = __float_as_uint(As[cur][r0 + g][kb + l]);
                af[m][1] = __float_as_uint(As[cur][r0 + g + 8][kb + l]);
                af[m][2] = __float_as_uint(As[cur][r0 + g][kb + l + 4]);
                af[m][3] = __float_as_uint(As[cur][r0 + g + 8][kb + l + 4]);
            }
            #pragma unroll
            for (int n = 0; n < 4; n++) {
                uint32_t bf[2];
                int nb = ng * 32 + n * 8 + g;
                bf[0] = __float_as_uint(Bs[cur][kb + l][nb]);
                bf[1] = __float_as_uint(Bs[cur][kb + l + 4][nb]);
                mma8(acc[0][n], af[0], bf);
                mma8(acc[1][n], af[1], bf);
            }
        }
        if (kc < 3) {
            #pragma unroll
            for (int jj = 0; jj < 8; jj++) As[nxt][arow][apart * 8 + jj] = tf32f(ar[jj] * gv);
            CPA_WAIT0();
        }
        __syncthreads();
    }

    // link reduction: each warp owns 32 cols
    {
        float p[4] = {0.f, 0.f, 0.f, 0.f};
        #pragma unroll
        for (int m = 0; m < 2; m++)
            #pragma unroll
            for (int n = 0; n < 4; n++) {
                int cb = ng * 32 + n * 8 + 2 * l;
                float u0 = u_s[cb], u1 = u_s[cb + 1];
                float e0 = bl1_s[cb], e1 = bl1_s[cb + 1];
                p[m*2+0] += fmaxf(acc[m][n][0] + e0, 0.f) * u0 + fmaxf(acc[m][n][1] + e1, 0.f) * u1;
                p[m*2+1] += fmaxf(acc[m][n][2] + e0, 0.f) * u0 + fmaxf(acc[m][n][3] + e1, 0.f) * u1;
            }
        #pragma unroll
        for (int q = 0; q < 4; q++) {
            p[q] += __shfl_xor_sync(0xffffffffu, p[q], 1);
            p[q] += __shfl_xor_sync(0xffffffffu, p[q], 2);
        }
        if (l == 0) {
            lpart[ng][mg * 32 + g]      = p[0];
            lpart[ng][mg * 32 + g + 8]  = p[1];
            lpart[ng][mg * 32 + 16 + g] = p[2];
            lpart[ng][mg * 32 + 24 + g] = p[3];
        }
    }
    __syncthreads();
    if (t < 64) {
        int ri2 = t >> 4, wi2 = t & 15;
        bool ok = (i0 + ri2 < V) && (w0 + wi2 < V);
        float sv = 0.f;
        if (ok) {
            int d = (b * NN + i0 + ri2) * NN + w0 + wi2;
            sv = (lpart[0][t] + lpart[1][t]) + (lpart[2][t] + lpart[3][t]) + b_l2[0];
            snext[d] = sv;
            if (out_adj) out_adj[d] = sv;
        }
        gates[t] = ok ? sigmoidf_(sv) : 0.f;   // reuse gates[] for sig(s_next)
    }

    // ---- fused m_sum on final pass: partial over this tile's 16 senders ----
    if (out_adj) {
        __syncthreads();
        const int r = t >> 6;                  // 0..3 receiver row
        const int c = (t & 63) * 2;            // 2 contiguous cols
        if (i0 + r < V) {
            const float* mp2 = g_mraw + (size_t)((b * NN + i0 + r) * NN + w0) * MD + c;
            float s0 = 0.f, s1 = 0.f;
            #pragma unroll
            for (int wq = 0; wq < 16; wq++) {
                float gq = gates[r * 16 + wq];
                float2 mv = *(const float2*)(mp2 + (size_t)wq * MD);
                s0 = fmaf(gq, mv.x, s0);
                s1 = fmaf(gq, mv.y, s1);
            }
            float* dst = &g_msum[(size_t)(b * NN + i0 + r) * MD + c];
            atomicAdd(dst, s0);
            atomicAdd(dst + 1, s1);
        }
    }
}

// ---------------- GRU + readout, 4 nodes per block ----------------
__global__ __launch_bounds__(128) void k_gru(
    const int* __restrict__ hn, const int* __restrict__ on,
    const float* __restrict__ W_ih, const float* __restrict__ b_ih,
    const float* __restrict__ W_hh, const float* __restrict__ b_hh,
    const float* __restrict__ W_ro, const float* __restrict__ b_ro,
    float* __restrict__ out)
{
    const int b  = blockIdx.y;
    const int V  = hn[b] + on[b];
    const int i0 = blockIdx.x * 4;
    const int t  = threadIdx.x;

    __shared__ float ms[4][MD];
    __shared__ float hsn[4][MD];
    __shared__ float hnew[4][MD];

    #pragma unroll
    for (int n = 0; n < 4; n++) {
        ms[n][t]  = g_msum[(size_t)(b * NN + i0 + n) * MD + t];
        hsn[n][t] = g_nf[(size_t)(b * NN + i0 + n) * MD + t];
    }
    __syncthreads();

    float air[4], aiz[4], ain[4], ahr[4], ahz[4], ahn[4];
    {
        float bir = b_ih[t], biz = b_ih[128 + t], bin_ = b_ih[256 + t];
        float bhr = b_hh[t], bhz = b_hh[128 + t], bhn = b_hh[256 + t];
        #pragma unroll
        for (int n = 0; n < 4; n++) {
            air[n] = bir; aiz[n] = biz; ain[n] = bin_;
            ahr[n] = bhr; ahz[n] = bhz; ahn[n] = bhn;
        }
    }
    #pragma unroll 2
    for (int k = 0; k < MD; k++) {
        float wr = W_ih[k * 384 + t];
        float wz = W_ih[k * 384 + 128 + t];
        float wn = W_ih[k * 384 + 256 + t];
        float vr = W_hh[k * 384 + t];
        float vz = W_hh[k * 384 + 128 + t];
        float vn = W_hh[k * 384 + 256 + t];
        #pragma unroll
        for (int n = 0; n < 4; n++) {
            float xv = ms[n][k], hv = hsn[n][k];
            air[n] = fmaf(xv, wr, air[n]);
            aiz[n] = fmaf(xv, wz, aiz[n]);
            ain[n] = fmaf(xv, wn, ain[n]);
            ahr[n] = fmaf(hv, vr, ahr[n]);
            ahz[n] = fmaf(hv, vz, ahz[n]);
            ahn[n] = fmaf(hv, vn, ahn[n]);
        }
    }
    #pragma unroll
    for (int n = 0; n < 4; n++) {
        float r   = sigmoidf_(air[n] + ahr[n]);
        float z   = sigmoidf_(aiz[n] + ahz[n]);
        float nn_ = tanhf(ain[n] + r * ahn[n]);
        hnew[n][t] = (1.f - z) * nn_ + z * hsn[n][t];
    }
    __syncthreads();

    float* lab = out + (size_t)BN * NN * NN;
    for (int cb = 0; cb < 5; cb++) {
        int c = cb * 128 + t;
        if (c >= CLS) continue;
        float lacc[4];
        #pragma unroll
        for (int n = 0; n < 4; n++) lacc[n] = 0.f;
        #pragma unroll 4
        for (int k = 0; k < MD; k++) {
            float wv = W_ro[k * CLS + c];
            #pragma unroll
            for (int n = 0; n < 4; n++) lacc[n] = fmaf(hnew[n][k], wv, lacc[n]);
        }
        float bv = b_ro[c];
        #pragma unroll
        for (int n = 0; n < 4; n++) {
            int i = i0 + n;
            float v = (i < V) ? (lacc[n] + bv) : 0.f;
            lab[(size_t)(b * NN + i) * CLS + c] = v;
        }
    }
}

// ---------------- launcher ----------------
extern "C" void kernel_launch(void* const* d_in, const int* in_sizes, int n_in,
                              void* d_out, int out_size)
{
    const float* edge_features = (const float*)d_in[0];
    const float* node_features = (const float*)d_in[1];
    const int*   human = (const int*)d_in[4];
    const int*   obj   = (const int*)d_in[5];
    const float* W_er  = (const float*)d_in[6];
    const float* b_er  = (const float*)d_in[7];
    const float* W_nr  = (const float*)d_in[8];
    const float* b_nr  = (const float*)d_in[9];
    const float* W_l1  = (const float*)d_in[10];
    const float* b_l1  = (const float*)d_in[11];
    const float* W_l2  = (const float*)d_in[12];
    const float* b_l2  = (const float*)d_in[13];
    const float* W_msg = (const float*)d_in[14];
    const float* b_msg = (const float*)d_in[15];
    const float* W_ih  = (const float*)d_in[16];
    const float* b_ih  = (const float*)d_in[17];
    const float* W_hh  = (const float*)d_in[18];
    const float* b_hh  = (const float*)d_in[19];
    const float* W_ro  = (const float*)d_in[20];
    const float* b_ro  = (const float*)d_in[21];
    float* out = (float*)d_out;

    k_prep<<<897, 256>>>(out, node_features, W_er, b_er, W_nr, b_nr, W_msg, b_msg, W_l1, b_l1);

    dim3 eg(NN / 16, NN / 4, BN);    // 16 x 64 x 4 = 4096 CTAs, 64 edges each
    k_edge_mma<<<eg, 256>>>(edge_features, human, obj, W_l2, b_l2);
    k_round_mma<<<eg, 256>>>(1, human, obj, b_l1, W_l2, b_l2, nullptr);
    k_round_mma<<<eg, 256>>>(2, human, obj, b_l1, W_l2, b_l2, out);   // + fused m_sum

    k_gru<<<dim3(NN / 4, BN), 128>>>(human, obj, W_ih, b_ih, W_hh, b_hh, W_ro, b_ro, out);
}